// round 2
// baseline (speedup 1.0000x reference)
#include <cuda_runtime.h>
#include <cstdint>

// Problem constants (fixed shapes from reference)
#define BATCH   8
#define SEQ     2048
#define DIM     512
#define QT      64          // queries per CTA
#define KT      32          // keys per inner tile
#define QSTR    520         // padded float stride for Q/K tiles
#define SST     33          // padded stride for score tile
#define NTHREADS 512        // 16 warps

// smem floats: Q 64x520, K 32x520, S 64x33, m/l/scale 3x64   (fp32, unrounded)
#define SMEM_FLOATS (QT*QSTR + KT*QSTR + QT*SST + 3*QT)
#define SMEM_BYTES  (SMEM_FLOATS * 4)

__device__ __forceinline__ uint32_t fu(float x) { return __float_as_uint(x); }

// Split fp32 into tf32-representable hi (truncate low 13 mantissa bits) and
// exact remainder lo. mma.tf32 truncates register low bits itself, so lo can
// be fed raw (its own truncation error is ~2^-22 relative to x).
__device__ __forceinline__ void split(float x, uint32_t& hi, uint32_t& lo) {
    uint32_t h = __float_as_uint(x) & 0xFFFFE000u;
    hi = h;
    lo = __float_as_uint(x - __uint_as_float(h));
}

__device__ __forceinline__ void mma8(float4& d,
                                     uint32_t a0, uint32_t a1, uint32_t a2, uint32_t a3,
                                     uint32_t b0, uint32_t b1) {
    asm volatile(
        "mma.sync.aligned.m16n8k8.row.col.f32.tf32.tf32.f32 "
        "{%0,%1,%2,%3},{%4,%5,%6,%7},{%8,%9},{%0,%1,%2,%3};"
        : "+f"(d.x), "+f"(d.y), "+f"(d.z), "+f"(d.w)
        : "r"(a0), "r"(a1), "r"(a2), "r"(a3), "r"(b0), "r"(b1));
}

__global__ void __launch_bounds__(NTHREADS, 1)
attn_flash_3xtf32(const float* __restrict__ enc,
                  const float* __restrict__ dec,
                  float* __restrict__ out) {
    extern __shared__ float sm[];
    float* sQ  = sm;                    // QT x QSTR (fp32)
    float* sK  = sQ + QT * QSTR;        // KT x QSTR (fp32)
    float* sS  = sK + KT * QSTR;        // QT x SST  (fp32 scores / P)
    float* sM  = sS + QT * SST;         // QT
    float* sL  = sM + QT;               // QT
    float* sSc = sL + QT;               // QT

    const int tid  = threadIdx.x;
    const int lane = tid & 31;
    const int wid  = tid >> 5;

    const int b  = blockIdx.x >> 5;           // 32 q-tiles per batch
    const int q0 = (blockIdx.x & 31) * QT;

    const float* decb = dec + ((size_t)b * SEQ + q0) * DIM;
    const float* encb = enc + (size_t)b * SEQ * DIM;

    // ---- load Q tile (raw fp32) ----
#pragma unroll
    for (int j = 0; j < 16; j++) {
        int i  = tid + j * NTHREADS;           // 64*128 = 8192 float4
        int r  = i >> 7;
        int c4 = (i & 127) << 2;
        *(float4*)(sQ + r * QSTR + c4) = *(const float4*)(decb + r * DIM + c4);
    }
    if (tid < QT) { sM[tid] = -1e30f; sL[tid] = 0.0f; }

    // GEMM1 warp coords: 4x4 warps over 64x32 score tile, each 16x8
    const int wm = wid >> 2;
    const int wn = wid & 3;
    // GEMM2 warp col base: 16 warps x 32 cols
    const int nbase = wid * 32;

    const int rl = lane >> 2;   // row-in-group
    const int cl = lane & 3;

    float4 o[4][4];
#pragma unroll
    for (int mt = 0; mt < 4; mt++)
#pragma unroll
        for (int nt = 0; nt < 4; nt++) o[mt][nt] = make_float4(0.f, 0.f, 0.f, 0.f);

    for (int kt = 0; kt < SEQ / KT; kt++) {
        __syncthreads();   // protect sK from previous GEMM2 readers

        // ---- load K tile (raw fp32) ----
        const float* kg = encb + (size_t)kt * KT * DIM;
#pragma unroll
        for (int j = 0; j < 8; j++) {
            int i  = tid + j * NTHREADS;       // 32*128 = 4096 float4
            int r  = i >> 7;
            int c4 = (i & 127) << 2;
            *(float4*)(sK + r * QSTR + c4) = *(const float4*)(kg + r * DIM + c4);
        }
        __syncthreads();

        // ---- GEMM1: S[64x32] = Q @ K^T over DIM=512, 3xTF32 ----
        float4 sa = make_float4(0.f, 0.f, 0.f, 0.f);
        {
            const float* q0p = sQ + (wm * 16 + rl) * QSTR + cl;
            const float* q1p = q0p + 8 * QSTR;
            const float* kp  = sK + (wn * 8 + rl) * QSTR + cl;
#pragma unroll 8
            for (int k = 0; k < DIM; k += 8) {
                uint32_t ah0, al0, ah1, al1, ah2, al2, ah3, al3;
                uint32_t bh0, bl0, bh1, bl1;
                split(q0p[k],     ah0, al0);
                split(q1p[k],     ah1, al1);
                split(q0p[k + 4], ah2, al2);
                split(q1p[k + 4], ah3, al3);
                split(kp[k],      bh0, bl0);
                split(kp[k + 4],  bh1, bl1);
                mma8(sa, ah0, ah1, ah2, ah3, bl0, bl1);   // hi*lo
                mma8(sa, al0, al1, al2, al3, bh0, bh1);   // lo*hi
                mma8(sa, ah0, ah1, ah2, ah3, bh0, bh1);   // hi*hi
            }
            int r = wm * 16 + rl;
            int c = wn * 8 + (cl << 1);
            sS[r * SST + c]           = sa.x;
            sS[r * SST + c + 1]       = sa.y;
            sS[(r + 8) * SST + c]     = sa.z;
            sS[(r + 8) * SST + c + 1] = sa.w;
        }
        __syncthreads();

        // ---- online softmax: 16 warps x 4 rows, 8 lanes per row ----
        {
            int row = (wid << 2) + (lane >> 3);
            int cb  = (lane & 7) << 2;
            float* sp = sS + row * SST + cb;
            float s0 = sp[0], s1 = sp[1], s2 = sp[2], s3 = sp[3];
            float mx = fmaxf(fmaxf(s0, s1), fmaxf(s2, s3));
            mx = fmaxf(mx, __shfl_xor_sync(0xffffffffu, mx, 1));
            mx = fmaxf(mx, __shfl_xor_sync(0xffffffffu, mx, 2));
            mx = fmaxf(mx, __shfl_xor_sync(0xffffffffu, mx, 4));
            float mo = sM[row];
            float mn = fmaxf(mo, mx);
            float p0 = __expf(s0 - mn), p1 = __expf(s1 - mn);
            float p2 = __expf(s2 - mn), p3 = __expf(s3 - mn);
            float su = p0 + p1 + p2 + p3;
            su += __shfl_xor_sync(0xffffffffu, su, 1);
            su += __shfl_xor_sync(0xffffffffu, su, 2);
            su += __shfl_xor_sync(0xffffffffu, su, 4);
            if ((lane & 7) == 0) {
                float sc = __expf(mo - mn);
                sSc[row] = sc;
                sM[row]  = mn;
                sL[row]  = sL[row] * sc + su;
            }
            // store P raw fp32 (GEMM2 splits at operand load)
            sp[0] = p0; sp[1] = p1; sp[2] = p2; sp[3] = p3;
        }
        __syncthreads();

        // ---- rescale O accumulators ----
        {
            float sc[8];
#pragma unroll
            for (int j = 0; j < 8; j++) sc[j] = sSc[rl + 8 * j];
#pragma unroll
            for (int mt = 0; mt < 4; mt++) {
                float slo = sc[2 * mt], shi = sc[2 * mt + 1];
#pragma unroll
                for (int nt = 0; nt < 4; nt++) {
                    o[mt][nt].x *= slo; o[mt][nt].y *= slo;
                    o[mt][nt].z *= shi; o[mt][nt].w *= shi;
                }
            }
        }

        // ---- GEMM2: O[64x512(warp:32)] += P[64x32] @ K[32x512], 3xTF32 ----
#pragma unroll
        for (int ks = 0; ks < 4; ks++) {
            const int k0 = ks * 8;
            // split B (K tile) for this warp's 32 cols
            uint32_t bh[4][2], bl[4][2];
            const float* bp = sK + (k0 + cl) * QSTR + nbase + rl;
#pragma unroll
            for (int nt = 0; nt < 4; nt++) {
                split(bp[nt * 8],            bh[nt][0], bl[nt][0]);
                split(bp[4 * QSTR + nt * 8], bh[nt][1], bl[nt][1]);
            }
#pragma unroll
            for (int mt = 0; mt < 4; mt++) {
                const float* pp = sS + (mt * 16 + rl) * SST + k0 + cl;
                uint32_t ah[4], al[4];
                split(pp[0],           ah[0], al[0]);
                split(pp[8 * SST],     ah[1], al[1]);
                split(pp[4],           ah[2], al[2]);
                split(pp[8 * SST + 4], ah[3], al[3]);
#pragma unroll
                for (int nt = 0; nt < 4; nt++) {
                    mma8(o[mt][nt], ah[0], ah[1], ah[2], ah[3], bl[nt][0], bl[nt][1]);
                    mma8(o[mt][nt], al[0], al[1], al[2], al[3], bh[nt][0], bh[nt][1]);
                    mma8(o[mt][nt], ah[0], ah[1], ah[2], ah[3], bh[nt][0], bh[nt][1]);
                }
            }
        }
    }

    __syncthreads();

    // ---- epilogue: normalize by 1/l and store ----
    {
        float il[8];
#pragma unroll
        for (int j = 0; j < 8; j++) il[j] = 1.0f / sL[rl + 8 * j];
        float* ob = out + ((size_t)b * SEQ + q0) * DIM;
#pragma unroll
        for (int mt = 0; mt < 4; mt++) {
            float ilo = il[2 * mt], ihi = il[2 * mt + 1];
            int r = mt * 16 + rl;
#pragma unroll
            for (int nt = 0; nt < 4; nt++) {
                int c = nbase + nt * 8 + (cl << 1);
                float2 v0 = make_float2(o[mt][nt].x * ilo, o[mt][nt].y * ilo);
                float2 v1 = make_float2(o[mt][nt].z * ihi, o[mt][nt].w * ihi);
                *(float2*)(ob + r * DIM + c)       = v0;
                *(float2*)(ob + (r + 8) * DIM + c) = v1;
            }
        }
    }
}

extern "C" void kernel_launch(void* const* d_in, const int* in_sizes, int n_in,
                              void* d_out, int out_size) {
    const float* enc = (const float*)d_in[0];   // enc_outputs [8,2048,512]
    const float* dec = (const float*)d_in[1];   // dec_outputs [8,2048,512]
    float* out = (float*)d_out;                 // [8,2048,512]

    cudaFuncSetAttribute(attn_flash_3xtf32,
                         cudaFuncAttributeMaxDynamicSharedMemorySize, SMEM_BYTES);

    dim3 grid(BATCH * (SEQ / QT));   // 256 CTAs
    attn_flash_3xtf32<<<grid, NTHREADS, SMEM_BYTES>>>(enc, dec, out);
}

// round 4
// speedup vs baseline: 1.6704x; 1.6704x over previous
#include <cuda_runtime.h>
#include <cuda_bf16.h>
#include <cstdint>

#define SEQ 2048
#define DIM 512
#define QT  64
#define KT  32
#define NTHREADS 512

#define QS32 260   // uint32 stride of pair-packed bf16 rows (256 pairs + 4 pad); 260 % 32 == 4
#define HSTR 520   // 16-bit element stride per row (= QS32*2)
#define SST  36    // float stride of score tile; 36 % 32 == 4
#define PS32 20    // uint32 stride of P pair rows (16 pairs + 4 pad); 20 % 32 == 20

// smem word layout (uint32 words)
#define W_Q0 0
#define W_Q1 (W_Q0 + QT*QS32)
#define W_K0 (W_Q1 + QT*QS32)
#define W_K1 (W_K0 + KT*QS32)
#define W_S  (W_K1 + KT*QS32)
#define W_P0 (W_S + QT*SST)
#define W_P1 (W_P0 + QT*PS32)
#define W_M  (W_P1 + QT*PS32)
#define W_L  (W_M + QT)
#define W_SC (W_L + QT)
#define SMEM_WORDS (W_SC + QT)
#define SMEM_BYTES (SMEM_WORDS * 4)   // 219,904 B

// split fp32 pair (x=even-k, y=odd-k) into bf16 hi-pair and exact-ish residual lo-pair
__device__ __forceinline__ void cvt2(float x, float y, uint32_t& hip, uint32_t& lop) {
    __nv_bfloat16 bx = __float2bfloat16_rn(x);
    __nv_bfloat16 by = __float2bfloat16_rn(y);
    float rx = x - __bfloat162float(bx);
    float ry = y - __bfloat162float(by);
    __nv_bfloat162 h; h.x = bx; h.y = by;           // .x = low half = even k
    __nv_bfloat162 l; l.x = __float2bfloat16_rn(rx); l.y = __float2bfloat16_rn(ry);
    hip = *reinterpret_cast<uint32_t*>(&h);
    lop = *reinterpret_cast<uint32_t*>(&l);
}

__device__ __forceinline__ void mma16(float4& d,
                                      uint32_t a0, uint32_t a1, uint32_t a2, uint32_t a3,
                                      uint32_t b0, uint32_t b1) {
    asm volatile(
        "mma.sync.aligned.m16n8k16.row.col.f32.bf16.bf16.f32 "
        "{%0,%1,%2,%3},{%4,%5,%6,%7},{%8,%9},{%0,%1,%2,%3};"
        : "+f"(d.x), "+f"(d.y), "+f"(d.z), "+f"(d.w)
        : "r"(a0), "r"(a1), "r"(a2), "r"(a3), "r"(b0), "r"(b1));
}

__global__ void __launch_bounds__(NTHREADS, 1)
attn_flash_bf16x2(const float* __restrict__ enc,
                  const float* __restrict__ dec,
                  float* __restrict__ out) {
    extern __shared__ uint32_t sm[];
    float* fS  = (float*)(sm + W_S);
    float* fM  = (float*)(sm + W_M);
    float* fL  = (float*)(sm + W_L);
    float* fSc = (float*)(sm + W_SC);

    const int tid  = threadIdx.x;
    const int lane = tid & 31;
    const int wid  = tid >> 5;
    const int g = lane >> 2;     // group (row) 0..7
    const int t = lane & 3;      // 0..3

    const int b  = blockIdx.x >> 5;
    const int q0 = (blockIdx.x & 31) * QT;

    const float* decb = dec + ((size_t)b * SEQ + q0) * DIM;
    const float* encb = enc + (size_t)b * SEQ * DIM;

    // ---- load Q tile, split to bf16 hi/lo pair tiles ----
#pragma unroll
    for (int j = 0; j < 16; j++) {
        int i  = tid + j * NTHREADS;        // 8192 float4
        int r  = i >> 7;
        int c4 = (i & 127) << 2;
        float4 v = *(const float4*)(decb + r * DIM + c4);
        uint32_t h0, l0, h1, l1;
        cvt2(v.x, v.y, h0, l0);
        cvt2(v.z, v.w, h1, l1);
        uint32_t w = r * QS32 + (c4 >> 1);
        *(uint2*)(sm + W_Q0 + w) = make_uint2(h0, h1);
        *(uint2*)(sm + W_Q1 + w) = make_uint2(l0, l1);
    }
    if (tid < QT) { fM[tid] = -1e30f; fL[tid] = 0.0f; }

    // GEMM1 warp grid: 4x4 warps, each 16x8 of the 64x32 score tile
    const int wm = wid >> 2;
    const int wn = wid & 3;
    const int nb = wid * 32;     // GEMM2 col slice

    float4 o[4][4];
#pragma unroll
    for (int mt = 0; mt < 4; mt++)
#pragma unroll
        for (int nt = 0; nt < 4; nt++) o[mt][nt] = make_float4(0.f, 0.f, 0.f, 0.f);

    for (int kt = 0; kt < SEQ / KT; kt++) {
        __syncthreads();   // protect K/P tiles from previous GEMM2 readers

        // ---- load K tile, split to bf16 hi/lo pair tiles ----
        const float* kg = encb + (size_t)kt * KT * DIM;
#pragma unroll
        for (int j = 0; j < 8; j++) {
            int i  = tid + j * NTHREADS;    // 4096 float4
            int r  = i >> 7;
            int c4 = (i & 127) << 2;
            float4 v = *(const float4*)(kg + r * DIM + c4);
            uint32_t h0, l0, h1, l1;
            cvt2(v.x, v.y, h0, l0);
            cvt2(v.z, v.w, h1, l1);
            uint32_t w = r * QS32 + (c4 >> 1);
            *(uint2*)(sm + W_K0 + w) = make_uint2(h0, h1);
            *(uint2*)(sm + W_K1 + w) = make_uint2(l0, l1);
        }
        __syncthreads();

        // ---- GEMM1: S[64x32] = Q @ K^T over DIM=512, 3-term split-bf16 ----
        {
            const uint32_t* q0p = sm + W_Q0 + (wm * 16 + g) * QS32 + t;
            const uint32_t* q1p = sm + W_Q1 + (wm * 16 + g) * QS32 + t;
            const uint32_t* k0p = sm + W_K0 + (wn * 8 + g) * QS32 + t;
            const uint32_t* k1p = sm + W_K1 + (wn * 8 + g) * QS32 + t;
            float4 c0 = make_float4(0.f, 0.f, 0.f, 0.f);
            float4 c1 = c0, c2 = c0;
#pragma unroll 8
            for (int s = 0; s < 32; s++) {
                int off = s * 8;
                uint32_t a0 = q0p[off],              a1 = q0p[off + 8 * QS32];
                uint32_t a2 = q0p[off + 4],          a3 = q0p[off + 8 * QS32 + 4];
                uint32_t b0 = k0p[off],              b1 = k0p[off + 4];
                uint32_t r0 = q1p[off],              r1 = q1p[off + 8 * QS32];
                uint32_t r2 = q1p[off + 4],          r3 = q1p[off + 8 * QS32 + 4];
                uint32_t s0 = k1p[off],              s1 = k1p[off + 4];
                mma16(c0, a0, a1, a2, a3, b0, b1);   // hi*hi
                mma16(c1, a0, a1, a2, a3, s0, s1);   // hi*lo
                mma16(c2, r0, r1, r2, r3, b0, b1);   // lo*hi
            }
            int r = wm * 16 + g;
            int c = wn * 8 + (t << 1);
            fS[r * SST + c]           = c0.x + c1.x + c2.x;
            fS[r * SST + c + 1]       = c0.y + c1.y + c2.y;
            fS[(r + 8) * SST + c]     = c0.z + c1.z + c2.z;
            fS[(r + 8) * SST + c + 1] = c0.w + c1.w + c2.w;
        }
        __syncthreads();

        // ---- online softmax: 16 warps x 4 rows, 8 lanes per row; emit P as bf16 hi/lo pairs ----
        {
            int row = (wid << 2) + (lane >> 3);
            int cb  = (lane & 7) << 2;
            float* sp = fS + row * SST + cb;
            float s0 = sp[0], s1 = sp[1], s2 = sp[2], s3 = sp[3];
            float mx = fmaxf(fmaxf(s0, s1), fmaxf(s2, s3));
            mx = fmaxf(mx, __shfl_xor_sync(0xffffffffu, mx, 1));
            mx = fmaxf(mx, __shfl_xor_sync(0xffffffffu, mx, 2));
            mx = fmaxf(mx, __shfl_xor_sync(0xffffffffu, mx, 4));
            float mo = fM[row];
            float mn = fmaxf(mo, mx);
            float p0 = __expf(s0 - mn), p1 = __expf(s1 - mn);
            float p2 = __expf(s2 - mn), p3 = __expf(s3 - mn);
            float su = p0 + p1 + p2 + p3;
            su += __shfl_xor_sync(0xffffffffu, su, 1);
            su += __shfl_xor_sync(0xffffffffu, su, 2);
            su += __shfl_xor_sync(0xffffffffu, su, 4);
            if ((lane & 7) == 0) {
                float sc = __expf(mo - mn);
                fSc[row] = sc;
                fM[row]  = mn;
                fL[row]  = fL[row] * sc + su;
            }
            uint32_t h0, l0, h1, l1;
            cvt2(p0, p1, h0, l0);
            cvt2(p2, p3, h1, l1);
            uint32_t w = row * PS32 + ((lane & 7) << 1);
            *(uint2*)(sm + W_P0 + w) = make_uint2(h0, h1);
            *(uint2*)(sm + W_P1 + w) = make_uint2(l0, l1);
        }
        __syncthreads();

        // ---- rescale O accumulators ----
        {
            float sc[8];
#pragma unroll
            for (int j = 0; j < 8; j++) sc[j] = fSc[g + 8 * j];
#pragma unroll
            for (int mt = 0; mt < 4; mt++) {
                float slo = sc[2 * mt], shi = sc[2 * mt + 1];
#pragma unroll
                for (int nt = 0; nt < 4; nt++) {
                    o[mt][nt].x *= slo; o[mt][nt].y *= slo;
                    o[mt][nt].z *= shi; o[mt][nt].w *= shi;
                }
            }
        }

        // ---- GEMM2: O[64 x (32/warp)] += P[64x32] @ K[32x512], 3-term split-bf16 ----
        {
            const unsigned short* k0h = (const unsigned short*)(sm + W_K0);
            const unsigned short* k1h = (const unsigned short*)(sm + W_K1);
#pragma unroll
            for (int ks = 0; ks < 2; ks++) {
                // A fragments: P hi (A0) and lo (A1) for all 4 m-tiles
                uint32_t A0[4][4], A1[4][4];
#pragma unroll
                for (int mt = 0; mt < 4; mt++) {
                    const uint32_t* pp0 = sm + W_P0 + (mt * 16 + g) * PS32 + t + ks * 8;
                    const uint32_t* pp1 = sm + W_P1 + (mt * 16 + g) * PS32 + t + ks * 8;
                    A0[mt][0] = pp0[0];  A0[mt][1] = pp0[8 * PS32];
                    A0[mt][2] = pp0[4];  A0[mt][3] = pp0[8 * PS32 + 4];
                    A1[mt][0] = pp1[0];  A1[mt][1] = pp1[8 * PS32];
                    A1[mt][2] = pp1[4];  A1[mt][3] = pp1[8 * PS32 + 4];
                }
                int kb = ks * 16;
#pragma unroll
                for (int nt = 0; nt < 4; nt++) {
                    int d = nb + nt * 8 + g;
                    int base = (kb + 2 * t) * HSTR + d;
                    uint32_t B00 = (uint32_t)k0h[base]            | ((uint32_t)k0h[base + HSTR]     << 16);
                    uint32_t B01 = (uint32_t)k0h[base + 8 * HSTR] | ((uint32_t)k0h[base + 9 * HSTR] << 16);
                    uint32_t B10 = (uint32_t)k1h[base]            | ((uint32_t)k1h[base + HSTR]     << 16);
                    uint32_t B11 = (uint32_t)k1h[base + 8 * HSTR] | ((uint32_t)k1h[base + 9 * HSTR] << 16);
#pragma unroll
                    for (int mt = 0; mt < 4; mt++) {
                        mma16(o[mt][nt], A0[mt][0], A0[mt][1], A0[mt][2], A0[mt][3], B00, B01); // p_hi*e_hi
                        mma16(o[mt][nt], A0[mt][0], A0[mt][1], A0[mt][2], A0[mt][3], B10, B11); // p_hi*e_lo
                        mma16(o[mt][nt], A1[mt][0], A1[mt][1], A1[mt][2], A1[mt][3], B00, B01); // p_lo*e_hi
                    }
                }
            }
        }
    }

    __syncthreads();

    // ---- epilogue: normalize by 1/l and store ----
    {
        float il[8];
#pragma unroll
        for (int j = 0; j < 8; j++) il[j] = 1.0f / fL[g + 8 * j];
        float* ob = out + ((size_t)b * SEQ + q0) * DIM;
#pragma unroll
        for (int mt = 0; mt < 4; mt++) {
            float ilo = il[2 * mt], ihi = il[2 * mt + 1];
            int r = mt * 16 + g;
#pragma unroll
            for (int nt = 0; nt < 4; nt++) {
                int c = nb + nt * 8 + (t << 1);
                float2 v0 = make_float2(o[mt][nt].x * ilo, o[mt][nt].y * ilo);
                float2 v1 = make_float2(o[mt][nt].z * ihi, o[mt][nt].w * ihi);
                *(float2*)(ob + r * DIM + c)       = v0;
                *(float2*)(ob + (r + 8) * DIM + c) = v1;
            }
        }
    }
}

extern "C" void kernel_launch(void* const* d_in, const int* in_sizes, int n_in,
                              void* d_out, int out_size) {
    const float* enc = (const float*)d_in[0];   // enc_outputs [8,2048,512]
    const float* dec = (const float*)d_in[1];   // dec_outputs [8,2048,512]
    float* out = (float*)d_out;                 // [8,2048,512]

    cudaFuncSetAttribute(attn_flash_bf16x2,
                         cudaFuncAttributeMaxDynamicSharedMemorySize, SMEM_BYTES);

    dim3 grid(8 * (SEQ / QT));   // 256 CTAs
    attn_flash_bf16x2<<<grid, NTHREADS, SMEM_BYTES>>>(enc, dec, out);
}